// round 2
// baseline (speedup 1.0000x reference)
#include <cuda_runtime.h>

#define B_    16
#define L_    512
#define H_    256
#define V_    32000
#define HALF_ 128
#define TOK   (B_*L_)   // 8192
#define H2_   (2*H_)    // 512

// ---------------- scratch (device globals; no allocation allowed) ----------------
__device__ float g_h  [TOK*H_];          // embedded tokens            8 MB
__device__ float g_hid[TOK*H2_];         // MLP hidden                16 MB
__device__ float g_x  [TOK*H_];          // h + ff                     8 MB
__device__ float g_hn [TOK*H_];          // LayerNorm output           8 MB
__device__ float g_ks [TOK*HALF_];       // semantic keys              4 MB
__device__ float g_ke [TOK*HALF_];       // episodic keys              4 MB
__device__ float g_kns[B_*(L_-1)*HALF_]; // normalized keys (t<L-1)    4 MB
__device__ float g_kne[B_*(L_-1)*HALF_];
__device__ float g_c  [B_*H_];
__device__ float g_r  [B_*H_];

// ---------------- embedding gather ----------------
__global__ void gather_kernel(const int* __restrict__ seq,
                              const float* __restrict__ embed,
                              float* __restrict__ h) {
    int tok = blockIdx.x;
    int t   = threadIdx.x;              // 256 threads = H
    h[tok*H_ + t] = embed[(long long)seq[tok]*H_ + t];
}

// ---------------- fp32 GEMM: C[M,N] = epi(A[M,K] @ B[N,K]^T) ----------------
// EPI: 0 = none, 1 = bias+relu, 2 = bias + residual add
template<int EPI>
__global__ void gemm_kernel(const float* __restrict__ A, const float* __restrict__ Bm,
                            const float* __restrict__ bias, const float* __restrict__ R,
                            float* __restrict__ C, int M, int N, int K) {
    const int BM = 128, BN = 64, BK = 16;
    __shared__ float As[BK][BM + 4];   // transposed A tile
    __shared__ float Bs[BK][BN + 4];   // transposed B tile

    int tid = threadIdx.x;             // 256
    int tx  = tid & 15;                // N dir
    int ty  = tid >> 4;                // M dir
    int m0  = blockIdx.y * BM;
    int n0  = blockIdx.x * BN;

    int lrow = tid >> 2;               // 0..63
    int lcol = (tid & 3) * 4;          // 0,4,8,12

    float acc[8][4];
#pragma unroll
    for (int i = 0; i < 8; i++)
#pragma unroll
        for (int j = 0; j < 4; j++) acc[i][j] = 0.f;

    for (int k0 = 0; k0 < K; k0 += BK) {
#pragma unroll
        for (int rr = 0; rr < 2; rr++) {
            int r = lrow + rr * 64;
            float4 v = *(const float4*)&A[(long long)(m0 + r)*K + k0 + lcol];
            As[lcol+0][r] = v.x; As[lcol+1][r] = v.y;
            As[lcol+2][r] = v.z; As[lcol+3][r] = v.w;
        }
        {
            float4 v = *(const float4*)&Bm[(long long)(n0 + lrow)*K + k0 + lcol];
            Bs[lcol+0][lrow] = v.x; Bs[lcol+1][lrow] = v.y;
            Bs[lcol+2][lrow] = v.z; Bs[lcol+3][lrow] = v.w;
        }
        __syncthreads();
#pragma unroll
        for (int k = 0; k < BK; k++) {
            float4 a0 = *(const float4*)&As[k][ty*8];
            float4 a1 = *(const float4*)&As[k][ty*8 + 4];
            float4 b0 = *(const float4*)&Bs[k][tx*4];
            float a[8] = {a0.x,a0.y,a0.z,a0.w,a1.x,a1.y,a1.z,a1.w};
            float b[4] = {b0.x,b0.y,b0.z,b0.w};
#pragma unroll
            for (int i = 0; i < 8; i++)
#pragma unroll
                for (int j = 0; j < 4; j++)
                    acc[i][j] += a[i] * b[j];
        }
        __syncthreads();
    }

#pragma unroll
    for (int i = 0; i < 8; i++) {
        int m = m0 + ty*8 + i;
#pragma unroll
        for (int j = 0; j < 4; j++) {
            int n = n0 + tx*4 + j;
            float v = acc[i][j];
            if (EPI == 1) { v += bias[n]; v = fmaxf(v, 0.f); }
            else if (EPI == 2) { v += bias[n] + R[(long long)m*N + n]; }
            C[(long long)m*N + n] = v;
        }
    }
}

// ---------------- LayerNorm over H=256 ----------------
__global__ void ln_kernel(const float* __restrict__ x, float* __restrict__ hn,
                          const float* __restrict__ gamma, const float* __restrict__ beta) {
    int row = blockIdx.x;
    int t   = threadIdx.x;             // 256
    float v = x[row*H_ + t];
    float a = v, b = v * v;
    __shared__ float s1[8], s2[8];
#pragma unroll
    for (int o = 16; o; o >>= 1) {
        a += __shfl_xor_sync(0xffffffffu, a, o);
        b += __shfl_xor_sync(0xffffffffu, b, o);
    }
    if ((t & 31) == 0) { s1[t >> 5] = a; s2[t >> 5] = b; }
    __syncthreads();
    if (t < 32) {
        a = (t < 8) ? s1[t] : 0.f;
        b = (t < 8) ? s2[t] : 0.f;
#pragma unroll
        for (int o = 4; o; o >>= 1) {
            a += __shfl_xor_sync(0xffffffffu, a, o);
            b += __shfl_xor_sync(0xffffffffu, b, o);
        }
        if (t == 0) { s1[0] = a; s2[0] = b; }
    }
    __syncthreads();
    float mu  = s1[0] * (1.0f / H_);
    float var = s2[0] * (1.0f / H_) - mu * mu;
    float inv = rsqrtf(var + 1e-5f);
    hn[row*H_ + t] = (v - mu) * inv * gamma[t] + beta[t];
}

// ---------------- key normalization (t = 0 .. L-2) ----------------
__global__ void knorm_kernel(const float* __restrict__ ks, const float* __restrict__ ke,
                             float* __restrict__ kns, float* __restrict__ kne) {
    int idx = blockIdx.x;              // B*(L-1)*2
    int m = idx & 1; idx >>= 1;
    int t = idx % (L_-1);
    int b = idx / (L_-1);
    const float* src = (m ? ke : ks) + ((long long)(b*L_ + t))*HALF_;
    float* dst = (m ? kne : kns) + ((long long)(b*(L_-1) + t))*HALF_;
    int i = threadIdx.x;               // 128
    float x = src[i];
    float ss = x * x;
#pragma unroll
    for (int o = 16; o; o >>= 1) ss += __shfl_xor_sync(0xffffffffu, ss, o);
    __shared__ float s[4];
    if ((i & 31) == 0) s[i >> 5] = ss;
    __syncthreads();
    float tot = s[0] + s[1] + s[2] + s[3];
    float n = sqrtf(tot);
    dst[i] = x / fmaxf(n, 1e-12f);
}

// ---------------- delta-rule scan: one warp per fast-weight row ----------------
// Row i of M evolves independently: M[i,:] += (k_t[i] - M[i,:].kn_t) * kn_t
__global__ void scan_kernel(const float* __restrict__ ks, const float* __restrict__ ke,
                            const float* __restrict__ kns, const float* __restrict__ kne,
                            float* __restrict__ c) {
    int bx = blockIdx.x;               // 512 = 16 batches * 2 matrices * 16 row groups
    int g  = bx & 15;
    int mm = (bx >> 4) & 1;
    int b  = bx >> 5;
    int w    = threadIdx.x >> 5;       // 8 warps
    int lane = threadIdx.x & 31;
    int row  = g * 8 + w;

    const float* kn = (mm ? kne : kns) + (long long)b*(L_-1)*HALF_;
    const float* kr = (mm ? ke  : ks ) + (long long)b*L_*HALF_;

    float4 s = make_float4(0.f, 0.f, 0.f, 0.f);
    for (int t = 0; t < L_-1; t++) {
        const float4 k4 = __ldg((const float4*)(kn + t*HALF_ + lane*4));
        float p = s.x*k4.x + s.y*k4.y + s.z*k4.z + s.w*k4.w;
#pragma unroll
        for (int o = 16; o; o >>= 1) p += __shfl_xor_sync(0xffffffffu, p, o);
        float kv = __ldg(kr + t*HALF_ + row);
        float d = kv - p;
        s.x += d*k4.x; s.y += d*k4.y; s.z += d*k4.z; s.w += d*k4.w;
    }
    // final read with raw last-token key
    const float4 q = __ldg((const float4*)(kr + (L_-1)*HALF_ + lane*4));
    float p = s.x*q.x + s.y*q.y + s.z*q.z + s.w*q.w;
#pragma unroll
    for (int o = 16; o; o >>= 1) p += __shfl_xor_sync(0xffffffffu, p, o);
    if (lane == 0) c[b*H_ + mm*HALF_ + row] = p;
}

// ---------------- r = c @ W_rp^T + b_rp ----------------
__global__ void rproj_kernel(const float* __restrict__ c, const float* __restrict__ W_rp,
                             const float* __restrict__ b_rp, float* __restrict__ r) {
    int b = blockIdx.x;
    int j = threadIdx.x;               // 256
    __shared__ float cs[H_];
    cs[j] = c[b*H_ + j];
    __syncthreads();
    float acc = b_rp[j];
    const float* w = W_rp + (long long)j*H_;
#pragma unroll 8
    for (int k = 0; k < H_; k++) acc += w[k] * cs[k];
    r[b*H_ + j] = acc;
}

// ---------------- out = r @ W_out^T + b_out  [16, 32000] ----------------
__global__ void out_kernel(const float* __restrict__ r, const float* __restrict__ W_out,
                           const float* __restrict__ b_out, float* __restrict__ out) {
    const int VB = 128, KC = 32;
    __shared__ float rs[B_*H_];                  // 16 KB
    __shared__ float ws[VB][KC + 4];             // 18 KB
    int tid = threadIdx.x;                       // 256
    int vl  = tid & (VB - 1);
    int v   = blockIdx.x * VB + vl;
    int bh  = tid >> 7;                          // batch half: 0 or 1
    for (int e = tid; e < B_*H_; e += 256) rs[e] = r[e];
    float acc[8];
#pragma unroll
    for (int b = 0; b < 8; b++) acc[b] = 0.f;

    for (int kc = 0; kc < H_; kc += KC) {
        __syncthreads();
        for (int e = tid; e < VB*KC; e += 256) {
            int i = e >> 5, j = e & 31;
            ws[i][j] = W_out[(long long)(blockIdx.x*VB + i)*H_ + kc + j];
        }
        __syncthreads();
#pragma unroll
        for (int k = 0; k < KC; k += 4) {
            float4 w4 = *(const float4*)&ws[vl][k];
#pragma unroll
            for (int b = 0; b < 8; b++) {
                float4 r4 = *(const float4*)&rs[(bh*8 + b)*H_ + kc + k];
                acc[b] += w4.x*r4.x + w4.y*r4.y + w4.z*r4.z + w4.w*r4.w;
            }
        }
    }
    float bo = b_out[v];
#pragma unroll
    for (int b = 0; b < 8; b++) out[(long long)(bh*8 + b)*V_ + v] = acc[b] + bo;
}

// ---------------- launch ----------------
extern "C" void kernel_launch(void* const* d_in, const int* in_sizes, int n_in,
                              void* d_out, int out_size) {
    const int*   seq   = (const int*)  d_in[0];
    const float* embed = (const float*)d_in[1];
    const float* W1    = (const float*)d_in[2];
    const float* b1    = (const float*)d_in[3];
    const float* W2    = (const float*)d_in[4];
    const float* b2    = (const float*)d_in[5];
    const float* gamma = (const float*)d_in[6];
    const float* beta  = (const float*)d_in[7];
    const float* W_sem = (const float*)d_in[8];
    const float* W_epi = (const float*)d_in[9];
    const float* W_rp  = (const float*)d_in[10];
    const float* b_rp  = (const float*)d_in[11];
    const float* W_out = (const float*)d_in[12];
    const float* b_out = (const float*)d_in[13];
    float* out = (float*)d_out;

    float *h, *hid, *x, *hn, *ks, *ke, *kns, *kne, *c, *r;
    cudaGetSymbolAddress((void**)&h,   g_h);
    cudaGetSymbolAddress((void**)&hid, g_hid);
    cudaGetSymbolAddress((void**)&x,   g_x);
    cudaGetSymbolAddress((void**)&hn,  g_hn);
    cudaGetSymbolAddress((void**)&ks,  g_ks);
    cudaGetSymbolAddress((void**)&ke,  g_ke);
    cudaGetSymbolAddress((void**)&kns, g_kns);
    cudaGetSymbolAddress((void**)&kne, g_kne);
    cudaGetSymbolAddress((void**)&c,   g_c);
    cudaGetSymbolAddress((void**)&r,   g_r);

    gather_kernel<<<TOK, H_>>>(seq, embed, h);

    // hidden = relu(h @ W1^T + b1)   [8192, 512]
    gemm_kernel<1><<<dim3(H2_/64, TOK/128), 256>>>(h, W1, b1, nullptr, hid, TOK, H2_, H_);
    // x = hidden @ W2^T + b2 + h     [8192, 256]
    gemm_kernel<2><<<dim3(H_/64, TOK/128), 256>>>(hid, W2, b2, h, x, TOK, H_, H2_);
    // hn = LN(x)*gamma + beta
    ln_kernel<<<TOK, H_>>>(x, hn, gamma, beta);
    // key projections
    gemm_kernel<0><<<dim3(HALF_/64, TOK/128), 256>>>(hn, W_sem, nullptr, nullptr, ks, TOK, HALF_, H_);
    gemm_kernel<0><<<dim3(HALF_/64, TOK/128), 256>>>(hn, W_epi, nullptr, nullptr, ke, TOK, HALF_, H_);
    // normalize keys for t < L-1
    knorm_kernel<<<B_*(L_-1)*2, HALF_>>>(ks, ke, kns, kne);
    // delta-rule scan + final read -> c [16, 256]
    scan_kernel<<<B_*2*16, 256>>>(ks, ke, kns, kne, c);
    // r = c @ W_rp^T + b_rp
    rproj_kernel<<<B_, H_>>>(c, W_rp, b_rp, r);
    // out = r @ W_out^T + b_out
    out_kernel<<<V_/128, 256>>>(r, W_out, b_out, out);
}

// round 4
// speedup vs baseline: 1.3054x; 1.3054x over previous
#include <cuda_runtime.h>
#include <cuda_bf16.h>
#include <cstdint>

#define B_    16
#define L_    512
#define H_    256
#define V_    32000
#define HALF_ 128
#define TOK   (B_*L_)   // 8192
#define H2_   (2*H_)    // 512

typedef __nv_bfloat16 bf16;

// ---------------- scratch (device globals) ----------------
__device__ __align__(16) float g_h  [TOK*H_];        // embedded tokens fp32 (residual)
__device__ __align__(16) bf16  g_hh [TOK*H_];        // h split hi
__device__ __align__(16) bf16  g_hl [TOK*H_];        // h split lo
__device__ __align__(16) bf16  g_W1h[H2_*H_], g_W1l[H2_*H_];
__device__ __align__(16) bf16  g_W2h[H_*H2_], g_W2l[H_*H2_];
__device__ __align__(16) bf16  g_Wkh[H_*H_],  g_Wkl[H_*H_];     // [W_sem; W_epi] 256x256
__device__ __align__(16) bf16  g_hidh[TOK*H2_], g_hidl[TOK*H2_];
__device__ __align__(16) float g_x  [TOK*H_];        // h + ff (pre-LN)
__device__ __align__(16) bf16  g_hnh[TOK*H_], g_hnl[TOK*H_];    // LN out split
__device__ __align__(16) float g_kraw[TOK*H_];       // [ks | ke] per token, stride 256
__device__ __align__(16) float g_kns[B_*(L_-1)*HALF_];
__device__ __align__(16) float g_kne[B_*(L_-1)*HALF_];
__device__ __align__(16) float g_c  [B_*H_];
__device__ __align__(16) float g_r  [B_*H_];

// ---------------- helpers ----------------
__device__ __forceinline__ void split2(float v, bf16& hi, bf16& lo) {
    hi = __float2bfloat16(v);
    lo = __float2bfloat16(v - __bfloat162float(hi));
}

// ---------------- weight split ----------------
__global__ void split_kernel(const float* __restrict__ src, bf16* __restrict__ hi,
                             bf16* __restrict__ lo, int n) {
    int i = blockIdx.x * 256 + threadIdx.x;
    if (i < n) { bf16 a, b; split2(src[i], a, b); hi[i] = a; lo[i] = b; }
}

// ---------------- embedding gather + split ----------------
__global__ void gather_kernel(const int* __restrict__ seq, const float* __restrict__ embed,
                              float* __restrict__ h, bf16* __restrict__ hh, bf16* __restrict__ hl) {
    int tok = blockIdx.x;
    int t   = threadIdx.x;            // 256
    float v = embed[(size_t)seq[tok]*H_ + t];
    h[tok*H_ + t] = v;
    bf16 a, b; split2(v, a, b);
    hh[tok*H_ + t] = a; hl[tok*H_ + t] = b;
}

// ---------------- bf16x3 split-GEMM: C[M,N] = epi(A @ B^T) ----------------
// A,B given as (hi,lo) bf16 pairs. EPI: 0=fp32 out, 1=bias+relu->bf16 split, 2=bias+residual->fp32
#define GBM 128
#define GBN 128
#define GBK 32
#define SLD (GBK + 8)                 // padded row stride (bf16 elems), 80B
#define GTILE (GBM * SLD)             // elems per tile array per stage
#define GSMEM (8 * GTILE * 2)         // bytes: 2 stages x 4 arrays

#define MMA_BF16(d, a, b) asm volatile( \
    "mma.sync.aligned.m16n8k16.row.col.f32.bf16.bf16.f32 " \
    "{%0,%1,%2,%3},{%4,%5,%6,%7},{%8,%9},{%0,%1,%2,%3};" \
    : "+f"(d[0]), "+f"(d[1]), "+f"(d[2]), "+f"(d[3]) \
    : "r"(a[0]), "r"(a[1]), "r"(a[2]), "r"(a[3]), "r"(b[0]), "r"(b[1]))

__device__ __forceinline__ void cp16(void* s, const void* g) {
    uint32_t sa = (uint32_t)__cvta_generic_to_shared(s);
    asm volatile("cp.async.cg.shared.global [%0], [%1], 16;\n" :: "r"(sa), "l"(g));
}

template<int EPI>
__global__ __launch_bounds__(256)
void gemm3_kernel(const bf16* __restrict__ Ah, const bf16* __restrict__ Al,
                  const bf16* __restrict__ Bh, const bf16* __restrict__ Bl,
                  const float* __restrict__ bias, const float* __restrict__ Rres,
                  float* __restrict__ Cf, bf16* __restrict__ Ch, bf16* __restrict__ Cl,
                  int M, int N, int K) {
    extern __shared__ bf16 smem[];
    bf16* As_h = smem;
    bf16* As_l = smem + 2*GTILE;
    bf16* Bs_h = smem + 4*GTILE;
    bf16* Bs_l = smem + 6*GTILE;

    const int tid  = threadIdx.x;
    const int wid  = tid >> 5;
    const int lane = tid & 31;
    const int wm   = (wid & 1) * 64;   // warp M offset within block
    const int wn   = (wid >> 1) * 32;  // warp N offset
    const int r    = lane >> 2;        // 0..7
    const int q    = lane & 3;         // 0..3
    const int m0   = blockIdx.y * GBM;
    const int n0   = blockIdx.x * GBN;

    float c[4][4][4];
#pragma unroll
    for (int mt = 0; mt < 4; mt++)
#pragma unroll
        for (int nt = 0; nt < 4; nt++)
#pragma unroll
            for (int e = 0; e < 4; e++) c[mt][nt][e] = 0.f;

    // tile loader (cp.async): 512 uint4 positions per array
    auto load_stage = [&](int st, int k0) {
#pragma unroll
        for (int i = tid; i < 512; i += 256) {
            int row = i >> 2, kc = (i & 3) * 8;
            size_t ga = (size_t)(m0 + row) * K + k0 + kc;
            size_t gb = (size_t)(n0 + row) * K + k0 + kc;
            int so = st * GTILE + row * SLD + kc;
            cp16(As_h + so, Ah + ga);
            cp16(As_l + so, Al + ga);
            cp16(Bs_h + so, Bh + gb);
            cp16(Bs_l + so, Bl + gb);
        }
        asm volatile("cp.async.commit_group;\n");
    };

    const int T = K / GBK;
    load_stage(0, 0);

    for (int t = 0; t < T; t++) {
        if (t + 1 < T) {
            load_stage((t + 1) & 1, (t + 1) * GBK);
            asm volatile("cp.async.wait_group 1;\n");
        } else {
            asm volatile("cp.async.wait_group 0;\n");
        }
        __syncthreads();

        const int st = (t & 1) * GTILE;
        const bf16* aph = As_h + st;
        const bf16* apl = As_l + st;
        const bf16* bph = Bs_h + st;
        const bf16* bpl = Bs_l + st;

#pragma unroll
        for (int kk = 0; kk < GBK; kk += 16) {
            uint32_t Afh[4][4], Afl[4][4], Bfh[4][2], Bfl[4][2];
#pragma unroll
            for (int mt = 0; mt < 4; mt++) {
                const bf16* ba = aph + (wm + mt*16 + r) * SLD + kk + q*2;
                Afh[mt][0] = *(const uint32_t*)ba;
                Afh[mt][1] = *(const uint32_t*)(ba + 8*SLD);
                Afh[mt][2] = *(const uint32_t*)(ba + 8);
                Afh[mt][3] = *(const uint32_t*)(ba + 8*SLD + 8);
                const bf16* bl_ = apl + (wm + mt*16 + r) * SLD + kk + q*2;
                Afl[mt][0] = *(const uint32_t*)bl_;
                Afl[mt][1] = *(const uint32_t*)(bl_ + 8*SLD);
                Afl[mt][2] = *(const uint32_t*)(bl_ + 8);
                Afl[mt][3] = *(const uint32_t*)(bl_ + 8*SLD + 8);
            }
#pragma unroll
            for (int nt = 0; nt < 4; nt++) {
                const bf16* bb = bph + (wn + nt*8 + r) * SLD + kk + q*2;
                Bfh[nt][0] = *(const uint32_t*)bb;
                Bfh[nt][1] = *(const uint32_t*)(bb + 8);
                const bf16* bc = bpl + (wn + nt*8 + r) * SLD + kk + q*2;
                Bfl[nt][0] = *(const uint32_t*)bc;
                Bfl[nt][1] = *(const uint32_t*)(bc + 8);
            }
#pragma unroll
            for (int mt = 0; mt < 4; mt++)
#pragma unroll
                for (int nt = 0; nt < 4; nt++) {
                    MMA_BF16(c[mt][nt], Afh[mt], Bfh[nt]);
                    MMA_BF16(c[mt][nt], Afh[mt], Bfl[nt]);
                    MMA_BF16(c[mt][nt], Afl[mt], Bfh[nt]);
                }
        }
        __syncthreads();
    }

    // epilogue
#pragma unroll
    for (int mt = 0; mt < 4; mt++)
#pragma unroll
        for (int nt = 0; nt < 4; nt++) {
            int gm = m0 + wm + mt*16 + r;
            int gn = n0 + wn + nt*8 + q*2;
#pragma unroll
            for (int half = 0; half < 2; half++) {
                int m = gm + half*8;
                float v0 = c[mt][nt][half*2 + 0];
                float v1 = c[mt][nt][half*2 + 1];
                size_t o = (size_t)m * N + gn;
                if (EPI == 1) {
                    v0 = fmaxf(v0 + bias[gn],     0.f);
                    v1 = fmaxf(v1 + bias[gn + 1], 0.f);
                    bf16 h0, l0, h1, l1;
                    split2(v0, h0, l0); split2(v1, h1, l1);
                    __nv_bfloat162 ph; ph.x = h0; ph.y = h1;
                    __nv_bfloat162 pl; pl.x = l0; pl.y = l1;
                    *(__nv_bfloat162*)&Ch[o] = ph;
                    *(__nv_bfloat162*)&Cl[o] = pl;
                } else if (EPI == 2) {
                    v0 += bias[gn]     + Rres[o];
                    v1 += bias[gn + 1] + Rres[o + 1];
                    float2 p; p.x = v0; p.y = v1;
                    *(float2*)&Cf[o] = p;
                } else {
                    float2 p; p.x = v0; p.y = v1;
                    *(float2*)&Cf[o] = p;
                }
            }
        }
}

// ---------------- LayerNorm: one warp per row, output bf16 split ----------------
__global__ void ln_kernel(const float* __restrict__ x, bf16* __restrict__ hh,
                          bf16* __restrict__ hl, const float* __restrict__ gamma,
                          const float* __restrict__ beta) {
    int row  = blockIdx.x * 8 + (threadIdx.x >> 5);
    int lane = threadIdx.x & 31;
    const float* xr = x + (size_t)row * H_ + lane * 8;
    float4 v0 = *(const float4*)xr;
    float4 v1 = *(const float4*)(xr + 4);
    float s  = v0.x+v0.y+v0.z+v0.w+v1.x+v1.y+v1.z+v1.w;
    float ss = v0.x*v0.x+v0.y*v0.y+v0.z*v0.z+v0.w*v0.w
             + v1.x*v1.x+v1.y*v1.y+v1.z*v1.z+v1.w*v1.w;
#pragma unroll
    for (int o = 16; o; o >>= 1) {
        s  += __shfl_xor_sync(0xffffffffu, s,  o);
        ss += __shfl_xor_sync(0xffffffffu, ss, o);
    }
    float mu  = s * (1.0f / H_);
    float var = ss * (1.0f / H_) - mu * mu;
    float inv = rsqrtf(var + 1e-5f);
    float4 g0 = *(const float4*)(gamma + lane*8);
    float4 g1 = *(const float4*)(gamma + lane*8 + 4);
    float4 b0 = *(const float4*)(beta  + lane*8);
    float4 b1 = *(const float4*)(beta  + lane*8 + 4);
    float y[8] = {
        (v0.x-mu)*inv*g0.x + b0.x, (v0.y-mu)*inv*g0.y + b0.y,
        (v0.z-mu)*inv*g0.z + b0.z, (v0.w-mu)*inv*g0.w + b0.w,
        (v1.x-mu)*inv*g1.x + b1.x, (v1.y-mu)*inv*g1.y + b1.y,
        (v1.z-mu)*inv*g1.z + b1.z, (v1.w-mu)*inv*g1.w + b1.w };
    bf16 oh[8], ol[8];
#pragma unroll
    for (int i = 0; i < 8; i++) split2(y[i], oh[i], ol[i]);
    *(uint4*)&hh[(size_t)row * H_ + lane*8] = *(uint4*)oh;
    *(uint4*)&hl[(size_t)row * H_ + lane*8] = *(uint4*)ol;
}

// ---------------- key normalization: one warp per (b, t, matrix) ----------------
__global__ void knorm_kernel(const float* __restrict__ kraw, float* __restrict__ kns,
                             float* __restrict__ kne) {
    int w = blockIdx.x * 8 + (threadIdx.x >> 5);
    int lane = threadIdx.x & 31;
    if (w >= B_ * (L_-1) * 2) return;
    int m = w & 1; int rest = w >> 1;
    int t = rest % (L_-1);
    int b = rest / (L_-1);
    const float* src = kraw + ((size_t)(b*L_ + t))*H_ + m*HALF_ + lane*4;
    float4 v = *(const float4*)src;
    float ss = v.x*v.x + v.y*v.y + v.z*v.z + v.w*v.w;
#pragma unroll
    for (int o = 16; o; o >>= 1) ss += __shfl_xor_sync(0xffffffffu, ss, o);
    float inv = 1.0f / fmaxf(sqrtf(ss), 1e-12f);
    float* dst = (m ? kne : kns) + ((size_t)(b*(L_-1) + t))*HALF_ + lane*4;
    float4 o4; o4.x = v.x*inv; o4.y = v.y*inv; o4.z = v.z*inv; o4.w = v.w*inv;
    *(float4*)dst = o4;
}

// ---------------- delta-rule scan: one warp per fast-weight row ----------------
__global__ void scan_kernel(const float* __restrict__ kraw,
                            const float* __restrict__ kns, const float* __restrict__ kne,
                            float* __restrict__ c) {
    int bx = blockIdx.x;               // 512 = 16 batches * 2 matrices * 16 row groups
    int g  = bx & 15;
    int mm = (bx >> 4) & 1;
    int b  = bx >> 5;
    int w    = threadIdx.x >> 5;       // 8 warps
    int lane = threadIdx.x & 31;
    int row  = g * 8 + w;

    const float* kn = (mm ? kne : kns) + (size_t)b*(L_-1)*HALF_;
    const float* kr = kraw + (size_t)b*L_*H_ + mm*HALF_;   // element (t,i): kr[t*H_ + i]

    float4 s = make_float4(0.f, 0.f, 0.f, 0.f);
    for (int t = 0; t < L_-1; t++) {
        const float4 k4 = __ldg((const float4*)(kn + t*HALF_ + lane*4));
        float p = s.x*k4.x + s.y*k4.y + s.z*k4.z + s.w*k4.w;
#pragma unroll
        for (int o = 16; o; o >>= 1) p += __shfl_xor_sync(0xffffffffu, p, o);
        float kv = __ldg(kr + t*H_ + row);
        float d = kv - p;
        s.x += d*k4.x; s.y += d*k4.y; s.z += d*k4.z; s.w += d*k4.w;
    }
    const float4 q = __ldg((const float4*)(kr + (L_-1)*H_ + lane*4));
    float p = s.x*q.x + s.y*q.y + s.z*q.z + s.w*q.w;
#pragma unroll
    for (int o = 16; o; o >>= 1) p += __shfl_xor_sync(0xffffffffu, p, o);
    if (lane == 0) c[b*H_ + mm*HALF_ + row] = p;
}

// ---------------- r = c @ W_rp^T + b_rp ----------------
__global__ void rproj_kernel(const float* __restrict__ c, const float* __restrict__ W_rp,
                             const float* __restrict__ b_rp, float* __restrict__ r) {
    int b = blockIdx.x;
    int j = threadIdx.x;               // 256
    __shared__ float cs[H_];
    cs[j] = c[b*H_ + j];
    __syncthreads();
    float acc = b_rp[j];
    const float* w = W_rp + (size_t)j*H_;
#pragma unroll 8
    for (int k = 0; k < H_; k++) acc += w[k] * cs[k];
    r[b*H_ + j] = acc;
}

// ---------------- out = r @ W_out^T + b_out  [16, 32000] ----------------
__global__ void out_kernel(const float* __restrict__ r, const float* __restrict__ W_out,
                           const float* __restrict__ b_out, float* __restrict__ out) {
    const int VB = 128, KC = 32;
    __shared__ float rs[B_*H_];
    __shared__ float ws[VB][KC + 4];
    int tid = threadIdx.x;
    int vl  = tid & (VB - 1);
    int v   = blockIdx.x * VB + vl;
    int bh  = tid >> 7;
    for (int e = tid; e < B_*H_; e += 256) rs[e] = r[e];
    float acc[8];
#pragma unroll
    for (int b = 0; b < 8; b++) acc[b] = 0.f;

    for (int kc = 0; kc < H_; kc += KC) {
        __syncthreads();
        for (int e = tid; e < VB*KC; e += 256) {
            int i = e >> 5, j = e & 31;
            ws[i][j] = W_out[(size_t)(blockIdx.x*VB + i)*H_ + kc + j];
        }
        __syncthreads();
#pragma unroll
        for (int k = 0; k < KC; k += 4) {
            float4 w4 = *(const float4*)&ws[vl][k];
#pragma unroll
            for (int b = 0; b < 8; b++) {
                float4 r4 = *(const float4*)&rs[(bh*8 + b)*H_ + kc + k];
                acc[b] += w4.x*r4.x + w4.y*r4.y + w4.z*r4.z + w4.w*r4.w;
            }
        }
    }
    float bo = b_out[v];
#pragma unroll
    for (int b = 0; b < 8; b++) out[(size_t)(bh*8 + b)*V_ + v] = acc[b] + bo;
}

// ---------------- launch ----------------
extern "C" void kernel_launch(void* const* d_in, const int* in_sizes, int n_in,
                              void* d_out, int out_size) {
    const int*   seq   = (const int*)  d_in[0];
    const float* embed = (const float*)d_in[1];
    const float* W1    = (const float*)d_in[2];
    const float* b1    = (const float*)d_in[3];
    const float* W2    = (const float*)d_in[4];
    const float* b2    = (const float*)d_in[5];
    const float* gamma = (const float*)d_in[6];
    const float* beta  = (const float*)d_in[7];
    const float* W_sem = (const float*)d_in[8];
    const float* W_epi = (const float*)d_in[9];
    const float* W_rp  = (const float*)d_in[10];
    const float* b_rp  = (const float*)d_in[11];
    const float* W_out = (const float*)d_in[12];
    const float* b_out = (const float*)d_in[13];
    float* out = (float*)d_out;

    float *h, *x, *kraw, *kns, *kne, *c, *r;
    bf16 *hh, *hl, *W1h, *W1l, *W2h, *W2l, *Wkh, *Wkl, *hidh, *hidl, *hnh, *hnl;
    cudaGetSymbolAddress((void**)&h,    g_h);
    cudaGetSymbolAddress((void**)&hh,   g_hh);
    cudaGetSymbolAddress((void**)&hl,   g_hl);
    cudaGetSymbolAddress((void**)&W1h,  g_W1h);
    cudaGetSymbolAddress((void**)&W1l,  g_W1l);
    cudaGetSymbolAddress((void**)&W2h,  g_W2h);
    cudaGetSymbolAddress((void**)&W2l,  g_W2l);
    cudaGetSymbolAddress((void**)&Wkh,  g_Wkh);
    cudaGetSymbolAddress((void**)&Wkl,  g_Wkl);
    cudaGetSymbolAddress((void**)&hidh, g_hidh);
    cudaGetSymbolAddress((void**)&hidl, g_hidl);
    cudaGetSymbolAddress((void**)&x,    g_x);
    cudaGetSymbolAddress((void**)&hnh,  g_hnh);
    cudaGetSymbolAddress((void**)&hnl,  g_hnl);
    cudaGetSymbolAddress((void**)&kraw, g_kraw);
    cudaGetSymbolAddress((void**)&kns,  g_kns);
    cudaGetSymbolAddress((void**)&kne,  g_kne);
    cudaGetSymbolAddress((void**)&c,    g_c);
    cudaGetSymbolAddress((void**)&r,    g_r);

    cudaFuncSetAttribute(gemm3_kernel<0>, cudaFuncAttributeMaxDynamicSharedMemorySize, GSMEM);
    cudaFuncSetAttribute(gemm3_kernel<1>, cudaFuncAttributeMaxDynamicSharedMemorySize, GSMEM);
    cudaFuncSetAttribute(gemm3_kernel<2>, cudaFuncAttributeMaxDynamicSharedMemorySize, GSMEM);

    // weight splits
    split_kernel<<<(H2_*H_ + 255)/256, 256>>>(W1, W1h, W1l, H2_*H_);
    split_kernel<<<(H_*H2_ + 255)/256, 256>>>(W2, W2h, W2l, H_*H2_);
    split_kernel<<<(HALF_*H_ + 255)/256, 256>>>(W_sem, Wkh, Wkl, HALF_*H_);
    split_kernel<<<(HALF_*H_ + 255)/256, 256>>>(W_epi, Wkh + HALF_*H_, Wkl + HALF_*H_, HALF_*H_);

    // embedding gather + split
    gather_kernel<<<TOK, H_>>>(seq, embed, h, hh, hl);

    // hid = relu(h @ W1^T + b1) -> bf16 split   [8192, 512]
    gemm3_kernel<1><<<dim3(H2_/GBN, TOK/GBM), 256, GSMEM>>>(
        hh, hl, W1h, W1l, b1, nullptr, nullptr, hidh, hidl, TOK, H2_, H_);
    // x = hid @ W2^T + b2 + h -> fp32           [8192, 256]
    gemm3_kernel<2><<<dim3(H_/GBN, TOK/GBM), 256, GSMEM>>>(
        hidh, hidl, W2h, W2l, b2, h, x, nullptr, nullptr, TOK, H_, H2_);
    // hn = LN(x) -> bf16 split
    ln_kernel<<<TOK/8, 256>>>(x, hnh, hnl, gamma, beta);
    // kraw = hn @ [W_sem; W_epi]^T -> fp32      [8192, 256]
    gemm3_kernel<0><<<dim3(H_/GBN, TOK/GBM), 256, GSMEM>>>(
        hnh, hnl, Wkh, Wkl, nullptr, nullptr, kraw, nullptr, nullptr, TOK, H_, H_);
    // normalize keys for t < L-1
    knorm_kernel<<<(B_*(L_-1)*2 + 7)/8, 256>>>(kraw, kns, kne);
    // delta-rule scan -> c [16, 256]
    scan_kernel<<<B_*2*16, 256>>>(kraw, kns, kne, c);
    // r = c @ W_rp^T + b_rp
    rproj_kernel<<<B_, H_>>>(c, W_rp, b_rp, r);
    // out = r @ W_out^T + b_out
    out_kernel<<<V_/128, 256>>>(r, W_out, b_out, out);
}

// round 5
// speedup vs baseline: 1.3397x; 1.0263x over previous
#include <cuda_runtime.h>
#include <cuda_bf16.h>
#include <cstdint>

#define B_    16
#define L_    512
#define H_    256
#define V_    32000
#define HALF_ 128
#define TOK   (B_*L_)   // 8192
#define H2_   (2*H_)    // 512
#define NBLK  127       // 4-step scan blocks (3 prologue + 127*4 = 511 steps)

typedef __nv_bfloat16 bf16;

// ---------------- scratch (device globals) ----------------
__device__ __align__(16) float g_h  [TOK*H_];
__device__ __align__(16) bf16  g_hh [TOK*H_];
__device__ __align__(16) bf16  g_hl [TOK*H_];
__device__ __align__(16) bf16  g_W1h[H2_*H_], g_W1l[H2_*H_];
__device__ __align__(16) bf16  g_W2h[H_*H2_], g_W2l[H_*H2_];
__device__ __align__(16) bf16  g_Wkh[H_*H_],  g_Wkl[H_*H_];
__device__ __align__(16) bf16  g_hidh[TOK*H2_], g_hidl[TOK*H2_];
__device__ __align__(16) float g_x  [TOK*H_];
__device__ __align__(16) bf16  g_hnh[TOK*H_], g_hnl[TOK*H_];
__device__ __align__(16) float g_kraw[TOK*H_];       // [ks | ke] per token, stride 256
__device__ __align__(16) float g_kns[B_*(L_-1)*HALF_];
__device__ __align__(16) float g_kne[B_*(L_-1)*HALF_];
__device__ __align__(16) float g_gram[B_*2*NBLK*6];  // pairwise dots per 4-step block
__device__ __align__(16) float g_c  [B_*H_];
__device__ __align__(16) float g_r  [B_*H_];

// ---------------- helpers ----------------
__device__ __forceinline__ void split2(float v, bf16& hi, bf16& lo) {
    hi = __float2bfloat16(v);
    lo = __float2bfloat16(v - __bfloat162float(hi));
}
__device__ __forceinline__ uint32_t s2u(const void* p) {
    return (uint32_t)__cvta_generic_to_shared(p);
}

// ---------------- merged weight split (one launch) ----------------
__global__ void split_all_kernel(const float* __restrict__ W1, const float* __restrict__ W2,
                                 const float* __restrict__ Wsem, const float* __restrict__ Wepi,
                                 bf16* __restrict__ W1h, bf16* __restrict__ W1l,
                                 bf16* __restrict__ W2h, bf16* __restrict__ W2l,
                                 bf16* __restrict__ Wkh, bf16* __restrict__ Wkl) {
    int i = blockIdx.x * 256 + threadIdx.x;   // total 327680
    const float* src; bf16 *hi, *lo; int off;
    if (i < 131072)      { src = W1;   hi = W1h; lo = W1l; off = i; }
    else if (i < 262144) { src = W2;   hi = W2h; lo = W2l; off = i - 131072; }
    else if (i < 294912) { src = Wsem; hi = Wkh; lo = Wkl; off = i - 262144; }
    else                 { src = Wepi; hi = Wkh + 32768; lo = Wkl + 32768; off = i - 294912; }
    bf16 a, b; split2(src[off], a, b);
    hi[off] = a; lo[off] = b;
}

// ---------------- embedding gather + split ----------------
__global__ void gather_kernel(const int* __restrict__ seq, const float* __restrict__ embed,
                              float* __restrict__ h, bf16* __restrict__ hh, bf16* __restrict__ hl) {
    int tok = blockIdx.x;
    int t   = threadIdx.x;            // 256
    float v = embed[(size_t)seq[tok]*H_ + t];
    h[tok*H_ + t] = v;
    bf16 a, b; split2(v, a, b);
    hh[tok*H_ + t] = a; hl[tok*H_ + t] = b;
}

// ---------------- bf16x3 split-GEMM with ldmatrix ----------------
#define GBM 128
#define GBN 128
#define GBK 32
#define SLD (GBK + 8)                 // padded row stride (bf16 elems), 80B
#define GTILE (GBM * SLD)
#define GSMEM (8 * GTILE * 2)

#define MMA_BF16(d, a, b) asm volatile( \
    "mma.sync.aligned.m16n8k16.row.col.f32.bf16.bf16.f32 " \
    "{%0,%1,%2,%3},{%4,%5,%6,%7},{%8,%9},{%0,%1,%2,%3};" \
    : "+f"(d[0]), "+f"(d[1]), "+f"(d[2]), "+f"(d[3]) \
    : "r"(a[0]), "r"(a[1]), "r"(a[2]), "r"(a[3]), "r"(b[0]), "r"(b[1]))

#define LDSM4(r0, r1, r2, r3, addr) asm volatile( \
    "ldmatrix.sync.aligned.m8n8.x4.shared.b16 {%0,%1,%2,%3}, [%4];" \
    : "=r"(r0), "=r"(r1), "=r"(r2), "=r"(r3) : "r"(addr))

__device__ __forceinline__ void cp16(void* s, const void* g) {
    asm volatile("cp.async.cg.shared.global [%0], [%1], 16;\n" :: "r"(s2u(s)), "l"(g));
}

template<int EPI>
__global__ __launch_bounds__(256)
void gemm3_kernel(const bf16* __restrict__ Ah, const bf16* __restrict__ Al,
                  const bf16* __restrict__ Bh, const bf16* __restrict__ Bl,
                  const float* __restrict__ bias, const float* __restrict__ Rres,
                  float* __restrict__ Cf, bf16* __restrict__ Ch, bf16* __restrict__ Cl,
                  int M, int N, int K) {
    extern __shared__ bf16 smem[];
    bf16* As_h = smem;
    bf16* As_l = smem + 2*GTILE;
    bf16* Bs_h = smem + 4*GTILE;
    bf16* Bs_l = smem + 6*GTILE;

    const int tid  = threadIdx.x;
    const int wid  = tid >> 5;
    const int lane = tid & 31;
    const int wm   = (wid & 1) * 64;
    const int wn   = (wid >> 1) * 32;
    const int r    = lane >> 2;
    const int q    = lane & 3;
    const int m0   = blockIdx.y * GBM;
    const int n0   = blockIdx.x * GBN;

    // ldmatrix lane addressing (element offsets within tile)
    const int aoff = (wm + (lane & 15)) * SLD + ((lane >> 4) * 8);
    const int boff = (wn + ((lane >> 4) * 8) + (lane & 7)) * SLD + (((lane >> 3) & 1) * 8);

    float c[4][4][4];
#pragma unroll
    for (int mt = 0; mt < 4; mt++)
#pragma unroll
        for (int nt = 0; nt < 4; nt++)
#pragma unroll
            for (int e = 0; e < 4; e++) c[mt][nt][e] = 0.f;

    auto load_stage = [&](int st, int k0) {
#pragma unroll
        for (int i = tid; i < 512; i += 256) {
            int row = i >> 2, kc = (i & 3) * 8;
            size_t ga = (size_t)(m0 + row) * K + k0 + kc;
            size_t gb = (size_t)(n0 + row) * K + k0 + kc;
            int so = st * GTILE + row * SLD + kc;
            cp16(As_h + so, Ah + ga);
            cp16(As_l + so, Al + ga);
            cp16(Bs_h + so, Bh + gb);
            cp16(Bs_l + so, Bl + gb);
        }
        asm volatile("cp.async.commit_group;\n");
    };

    const int T = K / GBK;
    load_stage(0, 0);

    for (int t = 0; t < T; t++) {
        if (t + 1 < T) {
            load_stage((t + 1) & 1, (t + 1) * GBK);
            asm volatile("cp.async.wait_group 1;\n");
        } else {
            asm volatile("cp.async.wait_group 0;\n");
        }
        __syncthreads();

        const int st = (t & 1) * GTILE;
        const uint32_t aBh = s2u(As_h + st + aoff);
        const uint32_t aBl = s2u(As_l + st + aoff);
        const uint32_t bBh = s2u(Bs_h + st + boff);
        const uint32_t bBl = s2u(Bs_l + st + boff);

#pragma unroll
        for (int kk = 0; kk < GBK; kk += 16) {
            const uint32_t ko = kk * 2;   // bytes
            uint32_t Afh[4][4], Afl[4][4], Bfh[4][2], Bfl[4][2];
#pragma unroll
            for (int mt = 0; mt < 4; mt++) {
                LDSM4(Afh[mt][0], Afh[mt][1], Afh[mt][2], Afh[mt][3],
                      aBh + (uint32_t)(mt * 16 * SLD * 2) + ko);
                LDSM4(Afl[mt][0], Afl[mt][1], Afl[mt][2], Afl[mt][3],
                      aBl + (uint32_t)(mt * 16 * SLD * 2) + ko);
            }
#pragma unroll
            for (int ntp = 0; ntp < 2; ntp++) {
                LDSM4(Bfh[2*ntp][0], Bfh[2*ntp][1], Bfh[2*ntp+1][0], Bfh[2*ntp+1][1],
                      bBh + (uint32_t)(ntp * 16 * SLD * 2) + ko);
                LDSM4(Bfl[2*ntp][0], Bfl[2*ntp][1], Bfl[2*ntp+1][0], Bfl[2*ntp+1][1],
                      bBl + (uint32_t)(ntp * 16 * SLD * 2) + ko);
            }
#pragma unroll
            for (int mt = 0; mt < 4; mt++)
#pragma unroll
                for (int nt = 0; nt < 4; nt++) {
                    MMA_BF16(c[mt][nt], Afh[mt], Bfh[nt]);
                    MMA_BF16(c[mt][nt], Afh[mt], Bfl[nt]);
                    MMA_BF16(c[mt][nt], Afl[mt], Bfh[nt]);
                }
        }
        __syncthreads();
    }

    // epilogue
#pragma unroll
    for (int mt = 0; mt < 4; mt++)
#pragma unroll
        for (int nt = 0; nt < 4; nt++) {
            int gm = m0 + wm + mt*16 + r;
            int gn = n0 + wn + nt*8 + q*2;
#pragma unroll
            for (int half = 0; half < 2; half++) {
                int m = gm + half*8;
                float v0 = c[mt][nt][half*2 + 0];
                float v1 = c[mt][nt][half*2 + 1];
                size_t o = (size_t)m * N + gn;
                if (EPI == 1) {
                    v0 = fmaxf(v0 + bias[gn],     0.f);
                    v1 = fmaxf(v1 + bias[gn + 1], 0.f);
                    bf16 h0, l0, h1, l1;
                    split2(v0, h0, l0); split2(v1, h1, l1);
                    __nv_bfloat162 ph; ph.x = h0; ph.y = h1;
                    __nv_bfloat162 pl; pl.x = l0; pl.y = l1;
                    *(__nv_bfloat162*)&Ch[o] = ph;
                    *(__nv_bfloat162*)&Cl[o] = pl;
                } else if (EPI == 2) {
                    v0 += bias[gn]     + Rres[o];
                    v1 += bias[gn + 1] + Rres[o + 1];
                    float2 p; p.x = v0; p.y = v1;
                    *(float2*)&Cf[o] = p;
                } else {
                    float2 p; p.x = v0; p.y = v1;
                    *(float2*)&Cf[o] = p;
                }
            }
        }
}

// ---------------- LayerNorm: one warp per row, output bf16 split ----------------
__global__ void ln_kernel(const float* __restrict__ x, bf16* __restrict__ hh,
                          bf16* __restrict__ hl, const float* __restrict__ gamma,
                          const float* __restrict__ beta) {
    int row  = blockIdx.x * 8 + (threadIdx.x >> 5);
    int lane = threadIdx.x & 31;
    const float* xr = x + (size_t)row * H_ + lane * 8;
    float4 v0 = *(const float4*)xr;
    float4 v1 = *(const float4*)(xr + 4);
    float s  = v0.x+v0.y+v0.z+v0.w+v1.x+v1.y+v1.z+v1.w;
    float ss = v0.x*v0.x+v0.y*v0.y+v0.z*v0.z+v0.w*v0.w
             + v1.x*v1.x+v1.y*v1.y+v1.z*v1.z+v1.w*v1.w;
#pragma unroll
    for (int o = 16; o; o >>= 1) {
        s  += __shfl_xor_sync(0xffffffffu, s,  o);
        ss += __shfl_xor_sync(0xffffffffu, ss, o);
    }
    float mu  = s * (1.0f / H_);
    float var = ss * (1.0f / H_) - mu * mu;
    float inv = rsqrtf(var + 1e-5f);
    float4 g0 = *(const float4*)(gamma + lane*8);
    float4 g1 = *(const float4*)(gamma + lane*8 + 4);
    float4 b0 = *(const float4*)(beta  + lane*8);
    float4 b1 = *(const float4*)(beta  + lane*8 + 4);
    float y[8] = {
        (v0.x-mu)*inv*g0.x + b0.x, (v0.y-mu)*inv*g0.y + b0.y,
        (v0.z-mu)*inv*g0.z + b0.z, (v0.w-mu)*inv*g0.w + b0.w,
        (v1.x-mu)*inv*g1.x + b1.x, (v1.y-mu)*inv*g1.y + b1.y,
        (v1.z-mu)*inv*g1.z + b1.z, (v1.w-mu)*inv*g1.w + b1.w };
    bf16 oh[8], ol[8];
#pragma unroll
    for (int i = 0; i < 8; i++) split2(y[i], oh[i], ol[i]);
    *(uint4*)&hh[(size_t)row * H_ + lane*8] = *(uint4*)oh;
    *(uint4*)&hl[(size_t)row * H_ + lane*8] = *(uint4*)ol;
}

// ---------------- key normalization ----------------
__global__ void knorm_kernel(const float* __restrict__ kraw, float* __restrict__ kns,
                             float* __restrict__ kne) {
    int w = blockIdx.x * 8 + (threadIdx.x >> 5);
    int lane = threadIdx.x & 31;
    if (w >= B_ * (L_-1) * 2) return;
    int m = w & 1; int rest = w >> 1;
    int t = rest % (L_-1);
    int b = rest / (L_-1);
    const float* src = kraw + ((size_t)(b*L_ + t))*H_ + m*HALF_ + lane*4;
    float4 v = *(const float4*)src;
    float ss = v.x*v.x + v.y*v.y + v.z*v.z + v.w*v.w;
#pragma unroll
    for (int o = 16; o; o >>= 1) ss += __shfl_xor_sync(0xffffffffu, ss, o);
    float inv = 1.0f / fmaxf(sqrtf(ss), 1e-12f);
    float* dst = (m ? kne : kns) + ((size_t)(b*(L_-1) + t))*HALF_ + lane*4;
    float4 o4; o4.x = v.x*inv; o4.y = v.y*inv; o4.z = v.z*inv; o4.w = v.w*inv;
    *(float4*)dst = o4;
}

// ---------------- pairwise Gram dots for 4-step scan blocks ----------------
// gram[(b*2+mm)*NBLK + blk][0..5] = {n0.n1, n0.n2, n0.n3, n1.n2, n1.n3, n2.n3}
// where nj = kn[t0+j], t0 = 3 + 4*blk
__global__ void gram_kernel(const float* __restrict__ kns, const float* __restrict__ kne,
                            float* __restrict__ gram) {
    int w = blockIdx.x * 8 + (threadIdx.x >> 5);
    int lane = threadIdx.x & 31;
    if (w >= B_ * 2 * NBLK) return;
    int blk = w % NBLK;
    int mm  = (w / NBLK) & 1;
    int b   = w / (NBLK * 2);
    const float* kn = (mm ? kne : kns) + (size_t)b*(L_-1)*HALF_;
    const float* base = kn + (size_t)(3 + blk*4)*HALF_ + lane*4;
    float4 n0 = *(const float4*)(base);
    float4 n1 = *(const float4*)(base + HALF_);
    float4 n2 = *(const float4*)(base + 2*HALF_);
    float4 n3 = *(const float4*)(base + 3*HALF_);
    float d01 = n0.x*n1.x + n0.y*n1.y + n0.z*n1.z + n0.w*n1.w;
    float d02 = n0.x*n2.x + n0.y*n2.y + n0.z*n2.z + n0.w*n2.w;
    float d03 = n0.x*n3.x + n0.y*n3.y + n0.z*n3.z + n0.w*n3.w;
    float d12 = n1.x*n2.x + n1.y*n2.y + n1.z*n2.z + n1.w*n2.w;
    float d13 = n1.x*n3.x + n1.y*n3.y + n1.z*n3.z + n1.w*n3.w;
    float d23 = n2.x*n3.x + n2.y*n3.y + n2.z*n3.z + n2.w*n3.w;
#pragma unroll
    for (int o = 16; o; o >>= 1) {
        d01 += __shfl_xor_sync(0xffffffffu, d01, o);
        d02 += __shfl_xor_sync(0xffffffffu, d02, o);
        d03 += __shfl_xor_sync(0xffffffffu, d03, o);
        d12 += __shfl_xor_sync(0xffffffffu, d12, o);
        d13 += __shfl_xor_sync(0xffffffffu, d13, o);
        d23 += __shfl_xor_sync(0xffffffffu, d23, o);
    }
    if (lane == 0) {
        float* gp = gram + (size_t)w * 6;
        gp[0] = d01; gp[1] = d02; gp[2] = d03;
        gp[3] = d12; gp[4] = d13; gp[5] = d23;
    }
}

// ---------------- 4-step blocked delta-rule scan ----------------
// Identity: s_j.n_j = s_0.n_j + sum_{i<j} d_i (n_i.n_j); Gram dots precomputed.
__global__ void scan_kernel(const float* __restrict__ kraw,
                            const float* __restrict__ kns, const float* __restrict__ kne,
                            const float* __restrict__ gram, float* __restrict__ c) {
    int bx = blockIdx.x;               // 512 = 16 batches * 2 matrices * 16 row groups
    int g  = bx & 15;
    int mm = (bx >> 4) & 1;
    int b  = bx >> 5;
    int w    = threadIdx.x >> 5;
    int lane = threadIdx.x & 31;
    int row  = g * 8 + w;

    const float* kn = (mm ? kne : kns) + (size_t)b*(L_-1)*HALF_;
    const float* kr = kraw + (size_t)b*L_*H_ + mm*HALF_;
    const float* gr = gram + (size_t)((b*2 + mm)*NBLK)*6;

    float4 s = make_float4(0.f, 0.f, 0.f, 0.f);

    // prologue: 3 single steps (t = 0, 1, 2)
#pragma unroll
    for (int t = 0; t < 3; t++) {
        const float4 k4 = __ldg((const float4*)(kn + t*HALF_ + lane*4));
        float p = s.x*k4.x + s.y*k4.y + s.z*k4.z + s.w*k4.w;
#pragma unroll
        for (int o = 16; o; o >>= 1) p += __shfl_xor_sync(0xffffffffu, p, o);
        float kv = __ldg(kr + t*H_ + row);
        float d = kv - p;
        s.x += d*k4.x; s.y += d*k4.y; s.z += d*k4.z; s.w += d*k4.w;
    }

    // 127 blocks of 4 steps
    for (int blk = 0; blk < NBLK; blk++) {
        const int t0 = 3 + blk*4;
        const float* base = kn + (size_t)t0*HALF_ + lane*4;
        const float4 n0 = __ldg((const float4*)(base));
        const float4 n1 = __ldg((const float4*)(base + HALF_));
        const float4 n2 = __ldg((const float4*)(base + 2*HALF_));
        const float4 n3 = __ldg((const float4*)(base + 3*HALF_));
        // issue uniform loads early (overlap with butterfly)
        const float* gp = gr + blk*6;
        float g01 = __ldg(gp+0), g02 = __ldg(gp+1), g03 = __ldg(gp+2);
        float g12 = __ldg(gp+3), g13 = __ldg(gp+4), g23 = __ldg(gp+5);
        const float* kb = kr + (size_t)t0*H_ + row;
        float k0 = __ldg(kb), k1 = __ldg(kb + H_), k2 = __ldg(kb + 2*H_), k3 = __ldg(kb + 3*H_);

        float p0 = s.x*n0.x + s.y*n0.y + s.z*n0.z + s.w*n0.w;
        float p1 = s.x*n1.x + s.y*n1.y + s.z*n1.z + s.w*n1.w;
        float p2 = s.x*n2.x + s.y*n2.y + s.z*n2.z + s.w*n2.w;
        float p3 = s.x*n3.x + s.y*n3.y + s.z*n3.z + s.w*n3.w;
#pragma unroll
        for (int o = 16; o; o >>= 1) {
            p0 += __shfl_xor_sync(0xffffffffu, p0, o);
            p1 += __shfl_xor_sync(0xffffffffu, p1, o);
            p2 += __shfl_xor_sync(0xffffffffu, p2, o);
            p3 += __shfl_xor_sync(0xffffffffu, p3, o);
        }
        float d0 = k0 - p0;
        float d1 = k1 - (p1 + d0*g01);
        float d2 = k2 - (p2 + d0*g02 + d1*g12);
        float d3 = k3 - (p3 + d0*g03 + d1*g13 + d2*g23);
        s.x += d0*n0.x + d1*n1.x + d2*n2.x + d3*n3.x;
        s.y += d0*n0.y + d1*n1.y + d2*n2.y + d3*n3.y;
        s.z += d0*n0.z + d1*n1.z + d2*n2.z + d3*n3.z;
        s.w += d0*n0.w + d1*n1.w + d2*n2.w + d3*n3.w;
    }

    // final read with raw last-token key
    const float4 q = __ldg((const float4*)(kr + (size_t)(L_-1)*H_ + lane*4));
    float p = s.x*q.x + s.y*q.y + s.z*q.z + s.w*q.w;
#pragma unroll
    for (int o = 16; o; o >>= 1) p += __shfl_xor_sync(0xffffffffu, p, o);
    if (lane == 0) c[b*H_ + mm*HALF_ + row] = p;
}

// ---------------- r = c @ W_rp^T + b_rp ----------------
__global__ void rproj_kernel(const float* __restrict__ c, const float* __restrict__ W_rp,
                             const float* __restrict__ b_rp, float* __restrict__ r) {
    int b = blockIdx.x;
    int j = threadIdx.x;
    __shared__ float cs[H_];
    cs[j] = c[b*H_ + j];
    __syncthreads();
    float acc = b_rp[j];
    const float* w = W_rp + (size_t)j*H_;
#pragma unroll 8
    for (int k = 0; k < H_; k++) acc += w[k] * cs[k];
    r[b*H_ + j] = acc;
}

// ---------------- out = r @ W_out^T + b_out  [16, 32000] ----------------
__global__ void out_kernel(const float* __restrict__ r, const float* __restrict__ W_out,
                           const float* __restrict__ b_out, float* __restrict__ out) {
    const int VB = 128, KC = 32;
    __shared__ float rs[B_*H_];
    __shared__ float ws[VB][KC + 4];
    int tid = threadIdx.x;
    int vl  = tid & (VB - 1);
    int v   = blockIdx.x * VB + vl;
    int bh  = tid >> 7;
    for (int e = tid; e < B_*H_; e += 256) rs[e] = r[e];
    float acc[8];
#pragma unroll
    for (int b = 0; b < 8; b++) acc[b] = 0.f;

    for (int kc = 0; kc < H_; kc += KC) {
        __syncthreads();
        for (int e = tid; e < VB*KC; e += 256) {
            int i = e >> 5, j = e & 31;
            ws[i][j] = W_out[(size_t)(blockIdx.x*VB + i)*H_ + kc + j];
        }
        __syncthreads();
#pragma unroll
        for (int k = 0; k < KC; k += 4) {
            float4 w4 = *(const float4*)&ws[vl][k];
#pragma unroll
            for (int b = 0; b < 8; b++) {
                float4 r4 = *(const float4*)&rs[(bh*8 + b)*H_ + kc + k];
                acc[b] += w4.x*r4.x + w4.y*r4.y + w4.z*r4.z + w4.w*r4.w;
            }
        }
    }
    float bo = b_out[v];
#pragma unroll
    for (int b = 0; b < 8; b++) out[(size_t)(bh*8 + b)*V_ + v] = acc[b] + bo;
}

// ---------------- launch ----------------
extern "C" void kernel_launch(void* const* d_in, const int* in_sizes, int n_in,
                              void* d_out, int out_size) {
    const int*   seq   = (const int*)  d_in[0];
    const float* embed = (const float*)d_in[1];
    const float* W1    = (const float*)d_in[2];
    const float* b1    = (const float*)d_in[3];
    const float* W2    = (const float*)d_in[4];
    const float* b2    = (const float*)d_in[5];
    const float* gamma = (const float*)d_in[6];
    const float* beta  = (const float*)d_in[7];
    const float* W_sem = (const float*)d_in[8];
    const float* W_epi = (const float*)d_in[9];
    const float* W_rp  = (const float*)d_in[10];
    const float* b_rp  = (const float*)d_in[11];
    const float* W_out = (const float*)d_in[12];
    const float* b_out = (const float*)d_in[13];
    float* out = (float*)d_out;

    float *h, *x, *kraw, *kns, *kne, *gram, *c, *r;
    bf16 *hh, *hl, *W1h, *W1l, *W2h, *W2l, *Wkh, *Wkl, *hidh, *hidl, *hnh, *hnl;
    cudaGetSymbolAddress((void**)&h,    g_h);
    cudaGetSymbolAddress((void**)&hh,   g_hh);
    cudaGetSymbolAddress((void**)&hl,   g_hl);
    cudaGetSymbolAddress((void**)&W1h,  g_W1h);
    cudaGetSymbolAddress((void**)&W1l,  g_W1l);
    cudaGetSymbolAddress((void**)&W2h,  g_W2h);
    cudaGetSymbolAddress((void**)&W2l,  g_W2l);
    cudaGetSymbolAddress((void**)&Wkh,  g_Wkh);
    cudaGetSymbolAddress((void**)&Wkl,  g_Wkl);
    cudaGetSymbolAddress((void**)&hidh, g_hidh);
    cudaGetSymbolAddress((void**)&hidl, g_hidl);
    cudaGetSymbolAddress((void**)&x,    g_x);
    cudaGetSymbolAddress((void**)&hnh,  g_hnh);
    cudaGetSymbolAddress((void**)&hnl,  g_hnl);
    cudaGetSymbolAddress((void**)&kraw, g_kraw);
    cudaGetSymbolAddress((void**)&kns,  g_kns);
    cudaGetSymbolAddress((void**)&kne,  g_kne);
    cudaGetSymbolAddress((void**)&gram, g_gram);
    cudaGetSymbolAddress((void**)&c,    g_c);
    cudaGetSymbolAddress((void**)&r,    g_r);

    cudaFuncSetAttribute(gemm3_kernel<0>, cudaFuncAttributeMaxDynamicSharedMemorySize, GSMEM);
    cudaFuncSetAttribute(gemm3_kernel<1>, cudaFuncAttributeMaxDynamicSharedMemorySize, GSMEM);
    cudaFuncSetAttribute(gemm3_kernel<2>, cudaFuncAttributeMaxDynamicSharedMemorySize, GSMEM);

    // 1: all weight splits in one launch (327680 elems)
    split_all_kernel<<<1280, 256>>>(W1, W2, W_sem, W_epi, W1h, W1l, W2h, W2l, Wkh, Wkl);
    // 2: embedding gather + split
    gather_kernel<<<TOK, H_>>>(seq, embed, h, hh, hl);
    // 3: hid = relu(h @ W1^T + b1) -> bf16 split   [8192, 512]
    gemm3_kernel<1><<<dim3(H2_/GBN, TOK/GBM), 256, GSMEM>>>(
        hh, hl, W1h, W1l, b1, nullptr, nullptr, hidh, hidl, TOK, H2_, H_);
    // 4: x = hid @ W2^T + b2 + h -> fp32           [8192, 256]
    gemm3_kernel<2><<<dim3(H_/GBN, TOK/GBM), 256, GSMEM>>>(
        hidh, hidl, W2h, W2l, b2, h, x, nullptr, nullptr, TOK, H_, H2_);
    // 5: hn = LN(x) -> bf16 split
    ln_kernel<<<TOK/8, 256>>>(x, hnh, hnl, gamma, beta);
    // 6: kraw = hn @ [W_sem; W_epi]^T -> fp32      [8192, 256]   (ncu -s 5 captures this)
    gemm3_kernel<0><<<dim3(H_/GBN, TOK/GBM), 256, GSMEM>>>(
        hnh, hnl, Wkh, Wkl, nullptr, nullptr, kraw, nullptr, nullptr, TOK, H_, H_);
    // 7: normalize keys for t < L-1
    knorm_kernel<<<(B_*(L_-1)*2 + 7)/8, 256>>>(kraw, kns, kne);
    // 8: pairwise Gram dots for scan blocks
    gram_kernel<<<(B_*2*NBLK + 7)/8, 256>>>(kns, kne, gram);
    // 9: blocked delta-rule scan -> c [16, 256]
    scan_kernel<<<B_*2*16, 256>>>(kraw, kns, kne, gram, c);
    // 10: r = c @ W_rp^T + b_rp
    rproj_kernel<<<B_, H_>>>(c, W_rp, b_rp, r);
    // 11: out = r @ W_out^T + b_out
    out_kernel<<<V_/128, 256>>>(r, W_out, b_out, out);
}

// round 6
// speedup vs baseline: 1.6433x; 1.2266x over previous
#include <cuda_runtime.h>
#include <cuda_bf16.h>
#include <cstdint>

#define B_    16
#define L_    512
#define H_    256
#define V_    32000
#define HALF_ 128
#define TOK   (B_*L_)   // 8192
#define H2_   (2*H_)    // 512
#define NBLK  127       // 4-step scan blocks at t0=4k (127*4=508) + 3 singles = 511

typedef __nv_bfloat16 bf16;
typedef unsigned long long ull;

// ---------------- scratch (device globals) ----------------
__device__ __align__(16) float g_h  [TOK*H_];
__device__ __align__(16) bf16  g_hh [TOK*H_];
__device__ __align__(16) bf16  g_hl [TOK*H_];
__device__ __align__(16) bf16  g_W1h[H2_*H_], g_W1l[H2_*H_];
__device__ __align__(16) bf16  g_W2h[H_*H2_], g_W2l[H_*H2_];
__device__ __align__(16) bf16  g_Wkh[H_*H_],  g_Wkl[H_*H_];
__device__ __align__(16) bf16  g_hidh[TOK*H2_], g_hidl[TOK*H2_];
__device__ __align__(16) float g_x  [TOK*H_];
__device__ __align__(16) bf16  g_hnh[TOK*H_], g_hnl[TOK*H_];
__device__ __align__(16) float g_kraw[TOK*H_];        // [ks | ke] per token, stride 256
__device__ __align__(16) float g_kns[B_*512*HALF_];   // padded to 512 timesteps
__device__ __align__(16) float g_kne[B_*512*HALF_];
__device__ __align__(16) float g_gram[B_*2*NBLK*8];   // 8-stride: {g01,g02,g03,g12,g13,g23,0,0}
__device__ __align__(16) float g_c  [B_*H_];
__device__ __align__(16) float g_r  [B_*H_];

// ---------------- helpers ----------------
__device__ __forceinline__ void split2(float v, bf16& hi, bf16& lo) {
    hi = __float2bfloat16(v);
    lo = __float2bfloat16(v - __bfloat162float(hi));
}
__device__ __forceinline__ uint32_t s2u(const void* p) {
    return (uint32_t)__cvta_generic_to_shared(p);
}
__device__ __forceinline__ void cp16(void* s, const void* g) {
    asm volatile("cp.async.cg.shared.global [%0], [%1], 16;\n" :: "r"(s2u(s)), "l"(g));
}
// packed f32x2
__device__ __forceinline__ ull pk2(float a, float b) {
    ull r; asm("mov.b64 %0, {%1, %2};" : "=l"(r) : "f"(a), "f"(b)); return r;
}
__device__ __forceinline__ float2 upk2(ull v) {
    float2 f; asm("mov.b64 {%0, %1}, %2;" : "=f"(f.x), "=f"(f.y) : "l"(v)); return f;
}
__device__ __forceinline__ ull ffma2(ull a, ull b, ull c) {
    ull d; asm("fma.rn.f32x2 %0, %1, %2, %3;" : "=l"(d) : "l"(a), "l"(b), "l"(c)); return d;
}
__device__ __forceinline__ ull fmul2(ull a, ull b) {
    ull d; asm("mul.rn.f32x2 %0, %1, %2;" : "=l"(d) : "l"(a), "l"(b)); return d;
}

// ---------------- merged weight split ----------------
__global__ void split_all_kernel(const float* __restrict__ W1, const float* __restrict__ W2,
                                 const float* __restrict__ Wsem, const float* __restrict__ Wepi,
                                 bf16* __restrict__ W1h, bf16* __restrict__ W1l,
                                 bf16* __restrict__ W2h, bf16* __restrict__ W2l,
                                 bf16* __restrict__ Wkh, bf16* __restrict__ Wkl) {
    int i = blockIdx.x * 256 + threadIdx.x;   // total 327680
    const float* src; bf16 *hi, *lo; int off;
    if (i < 131072)      { src = W1;   hi = W1h; lo = W1l; off = i; }
    else if (i < 262144) { src = W2;   hi = W2h; lo = W2l; off = i - 131072; }
    else if (i < 294912) { src = Wsem; hi = Wkh; lo = Wkl; off = i - 262144; }
    else                 { src = Wepi; hi = Wkh + 32768; lo = Wkl + 32768; off = i - 294912; }
    bf16 a, b; split2(src[off], a, b);
    hi[off] = a; lo[off] = b;
}

// ---------------- embedding gather + split ----------------
__global__ void gather_kernel(const int* __restrict__ seq, const float* __restrict__ embed,
                              float* __restrict__ h, bf16* __restrict__ hh, bf16* __restrict__ hl) {
    int tok = blockIdx.x;
    int t   = threadIdx.x;            // 256
    float v = embed[(size_t)seq[tok]*H_ + t];
    h[tok*H_ + t] = v;
    bf16 a, b; split2(v, a, b);
    hh[tok*H_ + t] = a; hl[tok*H_ + t] = b;
}

// ---------------- bf16x3 split-GEMM, 128x64 tiles, ldmatrix ----------------
#define GBM 128
#define GBN 64
#define GBK 32
#define SLD (GBK + 8)                 // padded row stride (bf16 elems), 80B
#define ATILE (GBM * SLD)             // 5120 elems
#define BTILE (GBN * SLD)             // 2560 elems
#define GSMEM ((4*ATILE + 4*BTILE) * 2)   // bytes = 61440

#define MMA_BF16(d, a, b) asm volatile( \
    "mma.sync.aligned.m16n8k16.row.col.f32.bf16.bf16.f32 " \
    "{%0,%1,%2,%3},{%4,%5,%6,%7},{%8,%9},{%0,%1,%2,%3};" \
    : "+f"(d[0]), "+f"(d[1]), "+f"(d[2]), "+f"(d[3]) \
    : "r"(a[0]), "r"(a[1]), "r"(a[2]), "r"(a[3]), "r"(b[0]), "r"(b[1]))

#define LDSM4(r0, r1, r2, r3, addr) asm volatile( \
    "ldmatrix.sync.aligned.m8n8.x4.shared.b16 {%0,%1,%2,%3}, [%4];" \
    : "=r"(r0), "=r"(r1), "=r"(r2), "=r"(r3) : "r"(addr))

template<int EPI>
__global__ __launch_bounds__(256, 2)
void gemm3_kernel(const bf16* __restrict__ Ah, const bf16* __restrict__ Al,
                  const bf16* __restrict__ Bh, const bf16* __restrict__ Bl,
                  const float* __restrict__ bias, const float* __restrict__ Rres,
                  float* __restrict__ Cf, bf16* __restrict__ Ch, bf16* __restrict__ Cl,
                  int M, int N, int K) {
    extern __shared__ bf16 smem[];
    bf16* As_h = smem;                          // 2*ATILE
    bf16* As_l = smem + 2*ATILE;                // 2*ATILE
    bf16* Bs_h = smem + 4*ATILE;                // 2*BTILE
    bf16* Bs_l = smem + 4*ATILE + 2*BTILE;      // 2*BTILE

    const int tid  = threadIdx.x;
    const int wid  = tid >> 5;
    const int lane = tid & 31;
    const int wm   = (wid & 3) * 32;    // 4 warps in M
    const int wn   = (wid >> 2) * 32;   // 2 warps in N
    const int r    = lane >> 2;
    const int q    = lane & 3;
    const int m0   = blockIdx.y * GBM;
    const int n0   = blockIdx.x * GBN;

    const int aoff = (wm + (lane & 15)) * SLD + ((lane >> 4) * 8);
    const int boff = (wn + ((lane >> 4) * 8) + (lane & 7)) * SLD + (((lane >> 3) & 1) * 8);

    float c[2][4][4];
#pragma unroll
    for (int mt = 0; mt < 2; mt++)
#pragma unroll
        for (int nt = 0; nt < 4; nt++)
#pragma unroll
            for (int e = 0; e < 4; e++) c[mt][nt][e] = 0.f;

    auto load_stage = [&](int st, int k0) {
#pragma unroll
        for (int i = tid; i < 512; i += 256) {       // A: 128 rows x 4 float4-cols
            int row = i >> 2, kc = (i & 3) * 8;
            size_t ga = (size_t)(m0 + row) * K + k0 + kc;
            int so = st * ATILE + row * SLD + kc;
            cp16(As_h + so, Ah + ga);
            cp16(As_l + so, Al + ga);
        }
        {                                            // B: 64 rows x 4 float4-cols
            int i = tid;                             // 256 positions
            int row = i >> 2, kc = (i & 3) * 8;
            size_t gb = (size_t)(n0 + row) * K + k0 + kc;
            int so = st * BTILE + row * SLD + kc;
            cp16(Bs_h + so, Bh + gb);
            cp16(Bs_l + so, Bl + gb);
        }
        asm volatile("cp.async.commit_group;\n");
    };

    const int T = K / GBK;
    load_stage(0, 0);

    for (int t = 0; t < T; t++) {
        if (t + 1 < T) {
            load_stage((t + 1) & 1, (t + 1) * GBK);
            asm volatile("cp.async.wait_group 1;\n");
        } else {
            asm volatile("cp.async.wait_group 0;\n");
        }
        __syncthreads();

        const uint32_t aBh = s2u(As_h + (t & 1) * ATILE + aoff);
        const uint32_t aBl = s2u(As_l + (t & 1) * ATILE + aoff);
        const uint32_t bBh = s2u(Bs_h + (t & 1) * BTILE + boff);
        const uint32_t bBl = s2u(Bs_l + (t & 1) * BTILE + boff);

#pragma unroll
        for (int kk = 0; kk < GBK; kk += 16) {
            const uint32_t ko = kk * 2;   // bytes
            uint32_t Afh[2][4], Afl[2][4], Bfh[4][2], Bfl[4][2];
#pragma unroll
            for (int mt = 0; mt < 2; mt++) {
                LDSM4(Afh[mt][0], Afh[mt][1], Afh[mt][2], Afh[mt][3],
                      aBh + (uint32_t)(mt * 16 * SLD * 2) + ko);
                LDSM4(Afl[mt][0], Afl[mt][1], Afl[mt][2], Afl[mt][3],
                      aBl + (uint32_t)(mt * 16 * SLD * 2) + ko);
            }
#pragma unroll
            for (int ntp = 0; ntp < 2; ntp++) {
                LDSM4(Bfh[2*ntp][0], Bfh[2*ntp][1], Bfh[2*ntp+1][0], Bfh[2*ntp+1][1],
                      bBh + (uint32_t)(ntp * 16 * SLD * 2) + ko);
                LDSM4(Bfl[2*ntp][0], Bfl[2*ntp][1], Bfl[2*ntp+1][0], Bfl[2*ntp+1][1],
                      bBl + (uint32_t)(ntp * 16 * SLD * 2) + ko);
            }
#pragma unroll
            for (int mt = 0; mt < 2; mt++)
#pragma unroll
                for (int nt = 0; nt < 4; nt++) {
                    MMA_BF16(c[mt][nt], Afh[mt], Bfh[nt]);
                    MMA_BF16(c[mt][nt], Afh[mt], Bfl[nt]);
                    MMA_BF16(c[mt][nt], Afl[mt], Bfh[nt]);
                }
        }
        __syncthreads();
    }

#pragma unroll
    for (int mt = 0; mt < 2; mt++)
#pragma unroll
        for (int nt = 0; nt < 4; nt++) {
            int gm = m0 + wm + mt*16 + r;
            int gn = n0 + wn + nt*8 + q*2;
#pragma unroll
            for (int half = 0; half < 2; half++) {
                int m = gm + half*8;
                float v0 = c[mt][nt][half*2 + 0];
                float v1 = c[mt][nt][half*2 + 1];
                size_t o = (size_t)m * N + gn;
                if (EPI == 1) {
                    v0 = fmaxf(v0 + bias[gn],     0.f);
                    v1 = fmaxf(v1 + bias[gn + 1], 0.f);
                    bf16 h0, l0, h1, l1;
                    split2(v0, h0, l0); split2(v1, h1, l1);
                    __nv_bfloat162 ph; ph.x = h0; ph.y = h1;
                    __nv_bfloat162 pl; pl.x = l0; pl.y = l1;
                    *(__nv_bfloat162*)&Ch[o] = ph;
                    *(__nv_bfloat162*)&Cl[o] = pl;
                } else if (EPI == 2) {
                    v0 += bias[gn]     + Rres[o];
                    v1 += bias[gn + 1] + Rres[o + 1];
                    float2 p; p.x = v0; p.y = v1;
                    *(float2*)&Cf[o] = p;
                } else {
                    float2 p; p.x = v0; p.y = v1;
                    *(float2*)&Cf[o] = p;
                }
            }
        }
}

// ---------------- LayerNorm: one warp per row, output bf16 split ----------------
__global__ void ln_kernel(const float* __restrict__ x, bf16* __restrict__ hh,
                          bf16* __restrict__ hl, const float* __restrict__ gamma,
                          const float* __restrict__ beta) {
    int row  = blockIdx.x * 8 + (threadIdx.x >> 5);
    int lane = threadIdx.x & 31;
    const float* xr = x + (size_t)row * H_ + lane * 8;
    float4 v0 = *(const float4*)xr;
    float4 v1 = *(const float4*)(xr + 4);
    float s  = v0.x+v0.y+v0.z+v0.w+v1.x+v1.y+v1.z+v1.w;
    float ss = v0.x*v0.x+v0.y*v0.y+v0.z*v0.z+v0.w*v0.w
             + v1.x*v1.x+v1.y*v1.y+v1.z*v1.z+v1.w*v1.w;
#pragma unroll
    for (int o = 16; o; o >>= 1) {
        s  += __shfl_xor_sync(0xffffffffu, s,  o);
        ss += __shfl_xor_sync(0xffffffffu, ss, o);
    }
    float mu  = s * (1.0f / H_);
    float var = ss * (1.0f / H_) - mu * mu;
    float inv = rsqrtf(var + 1e-5f);
    float4 g0 = *(const float4*)(gamma + lane*8);
    float4 g1 = *(const float4*)(gamma + lane*8 + 4);
    float4 b0 = *(const float4*)(beta  + lane*8);
    float4 b1 = *(const float4*)(beta  + lane*8 + 4);
    float y[8] = {
        (v0.x-mu)*inv*g0.x + b0.x, (v0.y-mu)*inv*g0.y + b0.y,
        (v0.z-mu)*inv*g0.z + b0.z, (v0.w-mu)*inv*g0.w + b0.w,
        (v1.x-mu)*inv*g1.x + b1.x, (v1.y-mu)*inv*g1.y + b1.y,
        (v1.z-mu)*inv*g1.z + b1.z, (v1.w-mu)*inv*g1.w + b1.w };
    bf16 oh[8], ol[8];
#pragma unroll
    for (int i = 0; i < 8; i++) split2(y[i], oh[i], ol[i]);
    *(uint4*)&hh[(size_t)row * H_ + lane*8] = *(uint4*)oh;
    *(uint4*)&hl[(size_t)row * H_ + lane*8] = *(uint4*)ol;
}

// ---------------- key normalization (padded 512-stride output) ----------------
__global__ void knorm_kernel(const float* __restrict__ kraw, float* __restrict__ kns,
                             float* __restrict__ kne) {
    int w = blockIdx.x * 8 + (threadIdx.x >> 5);
    int lane = threadIdx.x & 31;
    if (w >= B_ * (L_-1) * 2) return;
    int m = w & 1; int rest = w >> 1;
    int t = rest % (L_-1);
    int b = rest / (L_-1);
    const float* src = kraw + ((size_t)(b*L_ + t))*H_ + m*HALF_ + lane*4;
    float4 v = *(const float4*)src;
    float ss = v.x*v.x + v.y*v.y + v.z*v.z + v.w*v.w;
#pragma unroll
    for (int o = 16; o; o >>= 1) ss += __shfl_xor_sync(0xffffffffu, ss, o);
    float inv = 1.0f / fmaxf(sqrtf(ss), 1e-12f);
    float* dst = (m ? kne : kns) + ((size_t)(b*512 + t))*HALF_ + lane*4;
    float4 o4; o4.x = v.x*inv; o4.y = v.y*inv; o4.z = v.z*inv; o4.w = v.w*inv;
    *(float4*)dst = o4;
}

// ---------------- pairwise Gram dots, blocks at t0 = 4*blk ----------------
__global__ void gram_kernel(const float* __restrict__ kns, const float* __restrict__ kne,
                            float* __restrict__ gram) {
    int w = blockIdx.x * 8 + (threadIdx.x >> 5);
    int lane = threadIdx.x & 31;
    if (w >= B_ * 2 * NBLK) return;
    int blk = w % NBLK;
    int mm  = (w / NBLK) & 1;
    int b   = w / (NBLK * 2);
    const float* kn = (mm ? kne : kns) + (size_t)b*512*HALF_;
    const float* base = kn + (size_t)(4*blk)*HALF_ + lane*4;
    float4 n0 = *(const float4*)(base);
    float4 n1 = *(const float4*)(base + HALF_);
    float4 n2 = *(const float4*)(base + 2*HALF_);
    float4 n3 = *(const float4*)(base + 3*HALF_);
    float d01 = n0.x*n1.x + n0.y*n1.y + n0.z*n1.z + n0.w*n1.w;
    float d02 = n0.x*n2.x + n0.y*n2.y + n0.z*n2.z + n0.w*n2.w;
    float d03 = n0.x*n3.x + n0.y*n3.y + n0.z*n3.z + n0.w*n3.w;
    float d12 = n1.x*n2.x + n1.y*n2.y + n1.z*n2.z + n1.w*n2.w;
    float d13 = n1.x*n3.x + n1.y*n3.y + n1.z*n3.z + n1.w*n3.w;
    float d23 = n2.x*n3.x + n2.y*n3.y + n2.z*n3.z + n2.w*n3.w;
#pragma unroll
    for (int o = 16; o; o >>= 1) {
        d01 += __shfl_xor_sync(0xffffffffu, d01, o);
        d02 += __shfl_xor_sync(0xffffffffu, d02, o);
        d03 += __shfl_xor_sync(0xffffffffu, d03, o);
        d12 += __shfl_xor_sync(0xffffffffu, d12, o);
        d13 += __shfl_xor_sync(0xffffffffu, d13, o);
        d23 += __shfl_xor_sync(0xffffffffu, d23, o);
    }
    if (lane == 0) {
        float* gp = gram + (size_t)w * 8;
        float4 a; a.x = d01; a.y = d02; a.z = d03; a.w = d12;
        float4 bb; bb.x = d13; bb.y = d23; bb.z = 0.f; bb.w = 0.f;
        *(float4*)gp = a;
        *(float4*)(gp + 4) = bb;
    }
}

// ---------------- blocked delta-rule scan: SMEM-staged, 2 rows/warp ----------------
// 256 blocks = 32 pairs x 8 rowgroups; 8 warps x 2 rows = 16 rows/block.
__global__ __launch_bounds__(256)
void scan_kernel(const float* __restrict__ kraw,
                 const float* __restrict__ kns, const float* __restrict__ kne,
                 const float* __restrict__ gram, float* __restrict__ co) {
    __shared__ float ksm[2][32*HALF_];   // 2 x 16KB

    const int bx = blockIdx.x;
    const int rg = bx & 7;
    const int pr = bx >> 3;              // pair 0..31
    const int mm = pr & 1, b = pr >> 1;
    const int w = threadIdx.x >> 5, lane = threadIdx.x & 31;
    const int r0 = rg*16 + w*2;          // rows r0, r0+1

    const float* kn = (mm ? kne : kns) + (size_t)b*512*HALF_;
    const float* kr = kraw + (size_t)b*L_*H_ + mm*HALF_;   // (t,i) at kr[t*H_ + i]
    const float* gr = gram + (size_t)pr*NBLK*8;

    auto issue = [&](int cc) {
        const float* src = kn + (size_t)cc*32*HALF_;
        float* dst = ksm[cc & 1];
#pragma unroll
        for (int j = 0; j < 4; j++) {
            int pos = threadIdx.x + j*256;       // 1024 float4s
            cp16(dst + pos*4, src + pos*4);
        }
        asm volatile("cp.async.commit_group;\n");
    };

    ull s0a = 0, s0b = 0, s1a = 0, s1b = 0;      // packed f32x2 state per row

    issue(0); issue(1);

    for (int c = 0; c < 16; c++) {
        if (c == 15) asm volatile("cp.async.wait_group 0;\n");
        else         asm volatile("cp.async.wait_group 1;\n");
        __syncthreads();
        const float* buf = ksm[c & 1];
        const int nb = (c == 15) ? 7 : 8;
        for (int j = 0; j < nb; j++) {
            const int blk = c*8 + j;
            const int ts = j*4;
            ull na[4], nb2[4];
#pragma unroll
            for (int i = 0; i < 4; i++) {
                float4 n4 = *(const float4*)(buf + (ts+i)*HALF_ + lane*4);
                na[i] = pk2(n4.x, n4.y); nb2[i] = pk2(n4.z, n4.w);
            }
            float4 gv0 = *(const float4*)(gr + blk*8);
            float4 gv1 = *(const float4*)(gr + blk*8 + 4);
            const float* kb = kr + (size_t)(blk*4)*H_ + r0;
            float k00 = __ldg(kb),         k01 = __ldg(kb + H_);
            float k02 = __ldg(kb + 2*H_),  k03 = __ldg(kb + 3*H_);
            float k10 = __ldg(kb + 1),     k11 = __ldg(kb + H_ + 1);
            float k12 = __ldg(kb + 2*H_+1),k13 = __ldg(kb + 3*H_ + 1);

            // 8 dot partials (v[r*4+i])
            float v[8];
#pragma unroll
            for (int i = 0; i < 4; i++) {
                float2 ta = upk2(ffma2(s0b, nb2[i], fmul2(s0a, na[i])));
                v[i]   = ta.x + ta.y;
                float2 tb = upk2(ffma2(s1b, nb2[i], fmul2(s1a, na[i])));
                v[4+i] = tb.x + tb.y;
            }
            // transposed butterfly: value j ends summed in lanes (lane>>2)&7 == j
            float u0[4];
#pragma unroll
            for (int jj = 0; jj < 4; jj++) {
                float lo = v[jj], hi = v[jj+4];
                float mine = (lane & 16) ? hi : lo;
                float oth  = (lane & 16) ? lo : hi;
                u0[jj] = mine + __shfl_xor_sync(0xffffffffu, oth, 16);
            }
            float w0[2];
#pragma unroll
            for (int jj = 0; jj < 2; jj++) {
                float mine = (lane & 8) ? u0[jj+2] : u0[jj];
                float oth  = (lane & 8) ? u0[jj]   : u0[jj+2];
                w0[jj] = mine + __shfl_xor_sync(0xffffffffu, oth, 8);
            }
            {
                float mine = (lane & 4) ? w0[1] : w0[0];
                float oth  = (lane & 4) ? w0[0] : w0[1];
                float z = mine + __shfl_xor_sync(0xffffffffu, oth, 4);
                z += __shfl_xor_sync(0xffffffffu, z, 2);
                z += __shfl_xor_sync(0xffffffffu, z, 1);
                float p00 = __shfl_sync(0xffffffffu, z, 0);
                float p01 = __shfl_sync(0xffffffffu, z, 4);
                float p02 = __shfl_sync(0xffffffffu, z, 8);
                float p03 = __shfl_sync(0xffffffffu, z, 12);
                float p10 = __shfl_sync(0xffffffffu, z, 16);
                float p11 = __shfl_sync(0xffffffffu, z, 20);
                float p12 = __shfl_sync(0xffffffffu, z, 24);
                float p13 = __shfl_sync(0xffffffffu, z, 28);
                // fixup (g01=gv0.x g02=gv0.y g03=gv0.z g12=gv0.w g13=gv1.x g23=gv1.y)
                float d00 = k00 - p00;
                float d01 = k01 - p01 - d00*gv0.x;
                float d02 = k02 - p02 - d00*gv0.y - d01*gv0.w;
                float d03 = k03 - p03 - d00*gv0.z - d01*gv1.x - d02*gv1.y;
                float d10 = k10 - p10;
                float d11 = k11 - p11 - d10*gv0.x;
                float d12v= k12 - p12 - d10*gv0.y - d11*gv0.w;
                float d13v= k13 - p13 - d10*gv0.z - d11*gv1.x - d12v*gv1.y;
                // updates
                ull D;
                D = pk2(d00, d00); s0a = ffma2(D, na[0], s0a); s0b = ffma2(D, nb2[0], s0b);
                D = pk2(d01, d01); s0a = ffma2(D, na[1], s0a); s0b = ffma2(D, nb2[1], s0b);
                D = pk2(d02, d02); s0a = ffma2(D, na[2], s0a); s0b = ffma2(D, nb2[2], s0b);
                D = pk2(d03, d03); s0a = ffma2(D, na[3], s0a); s0b = ffma2(D, nb2[3], s0b);
                D = pk2(d10, d10); s1a = ffma2(D, na[0], s1a); s1b = ffma2(D, nb2[0], s1b);
                D = pk2(d11, d11); s1a = ffma2(D, na[1], s1a); s1b = ffma2(D, nb2[1], s1b);
                D = pk2(d12v,d12v);s1a = ffma2(D, na[2], s1a); s1b = ffma2(D, nb2[2], s1b);
                D = pk2(d13v,d13v);s1a = ffma2(D, na[3], s1a); s1b = ffma2(D, nb2[3], s1b);
            }
        }
        __syncthreads();
        if (c + 2 < 16) issue(c + 2);
    }

    // singles t = 508..510 (chunk 15 buffer = ksm[1])
    {
        const float* buf = ksm[1];
        for (int t = 508; t <= 510; t++) {
            float4 n4 = *(const float4*)(buf + (t-480)*HALF_ + lane*4);
            ull na = pk2(n4.x, n4.y), nb2 = pk2(n4.z, n4.w);
            float2 ta = upk2(ffma2(s0b, nb2, fmul2(s0a, na)));
            float p0 = ta.x + ta.y;
            float2 tb = upk2(ffma2(s1b, nb2, fmul2(s1a, na)));
            float p1 = tb.x + tb.y;
#pragma unroll
            for (int o = 16; o; o >>= 1) {
                p0 += __shfl_xor_sync(0xffffffffu, p0, o);
                p1 += __shfl_xor_sync(0xffffffffu, p1, o);
            }
            float k0v = __ldg(kr + (size_t)t*H_ + r0);
            float k1v = __ldg(kr + (size_t)t*H_ + r0 + 1);
            ull D0 = pk2(k0v - p0, k0v - p0);
            ull D1 = pk2(k1v - p1, k1v - p1);
            s0a = ffma2(D0, na, s0a); s0b = ffma2(D0, nb2, s0b);
            s1a = ffma2(D1, na, s1a); s1b = ffma2(D1, nb2, s1b);
        }
    }

    // final read with raw last-token key (t = 511)
    {
        float4 q4 = *(const float4*)(kr + (size_t)511*H_ + lane*4);
        ull qa = pk2(q4.x, q4.y), qb = pk2(q4.z, q4.w);
        float2 ta = upk2(ffma2(s0b, qb, fmul2(s0a, qa)));
        float p0 = ta.x + ta.y;
        float2 tb = upk2(ffma2(s1b, qb, fmul2(s1a, qa)));
        float p1 = tb.x + tb.y;
#pragma unroll
        for (int o = 16; o; o >>= 1) {
            p0 += __shfl_xor_sync(0xffffffffu, p0, o);
            p1 += __shfl_xor_sync(0xffffffffu, p1, o);
        }
        if (lane == 0) {
            co[b*H_ + mm*HALF_ + r0]     = p0;
            co[b*H_ + mm*HALF_ + r0 + 1] = p1;
        }
    }
}

// ---------------- r = c @ W_rp^T + b_rp ----------------
__global__ void rproj_kernel(const float* __restrict__ c, const float* __restrict__ W_rp,
                             const float* __restrict__ b_rp, float* __restrict__ r) {
    int b = blockIdx.x;
    int j = threadIdx.x;
    __shared__ float cs[H_];
    cs[j] = c[b*H_ + j];
    __syncthreads();
    float acc = b_rp[j];
    const float* w = W_rp + (size_t)j*H_;
#pragma unroll 8
    for (int k = 0; k < H_; k++) acc += w[k] * cs[k];
    r[b*H_ + j] = acc;
}

// ---------------- out = r @ W_out^T + b_out  [16, 32000] ----------------
__global__ void out_kernel(const float* __restrict__ r, const float* __restrict__ W_out,
                           const float* __restrict__ b_out, float* __restrict__ out) {
    const int VB = 128, KC = 32;
    __shared__ float rs[B_*H_];
    __shared__ float ws[VB][KC + 4];
    int tid = threadIdx.x;
    int vl  = tid & (VB - 1);
    int v   = blockIdx.x * VB + vl;
    int bh  = tid >> 7;
    for (int e = tid; e < B_*H_; e += 256) rs[e] = r[e];
    float acc[8];
#pragma unroll
    for (int b = 0; b < 8; b++) acc[b] = 0.f;

    for (int kc = 0; kc < H_; kc += KC) {
        __syncthreads();
        for (int e = tid; e < VB*KC; e += 256) {
            int i = e >> 5, j = e & 31;
            ws[i][j] = W_out[(size_t)(blockIdx.x*VB + i)*H_ + kc + j];
        }
        __syncthreads();
#pragma unroll
        for (int k = 0; k < KC; k += 4) {
            float4 w4 = *(const float4*)&ws[vl][k];
#pragma unroll
            for (int b = 0; b < 8; b++) {
                float4 r4 = *(const float4*)&rs[(bh*8 + b)*H_ + kc + k];
                acc[b] += w4.x*r4.x + w4.y*r4.y + w4.z*r4.z + w4.w*r4.w;
            }
        }
    }
    float bo = b_out[v];
#pragma unroll
    for (int b = 0; b < 8; b++) out[(size_t)(bh*8 + b)*V_ + v] = acc[b] + bo;
}

// ---------------- launch ----------------
extern "C" void kernel_launch(void* const* d_in, const int* in_sizes, int n_in,
                              void* d_out, int out_size) {
    const int*   seq   = (const int*)  d_in[0];
    const float* embed = (const float*)d_in[1];
    const float* W1    = (const float*)d_in[2];
    const float* b1    = (const float*)d_in[3];
    const float* W2    = (const float*)d_in[4];
    const float* b2    = (const float*)d_in[5];
    const float* gamma = (const float*)d_in[6];
    const float* beta  = (const float*)d_in[7];
    const float* W_sem = (const float*)d_in[8];
    const float* W_epi = (const float*)d_in[9];
    const float* W_rp  = (const float*)d_in[10];
    const float* b_rp  = (const float*)d_in[11];
    const float* W_out = (const float*)d_in[12];
    const float* b_out = (const float*)d_in[13];
    float* out = (float*)d_out;

    float *h, *x, *kraw, *kns, *kne, *gram, *c, *r;
    bf16 *hh, *hl, *W1h, *W1l, *W2h, *W2l, *Wkh, *Wkl, *hidh, *hidl, *hnh, *hnl;
    cudaGetSymbolAddress((void**)&h,    g_h);
    cudaGetSymbolAddress((void**)&hh,   g_hh);
    cudaGetSymbolAddress((void**)&hl,   g_hl);
    cudaGetSymbolAddress((void**)&W1h,  g_W1h);
    cudaGetSymbolAddress((void**)&W1l,  g_W1l);
    cudaGetSymbolAddress((void**)&W2h,  g_W2h);
    cudaGetSymbolAddress((void**)&W2l,  g_W2l);
    cudaGetSymbolAddress((void**)&Wkh,  g_Wkh);
    cudaGetSymbolAddress((void**)&Wkl,  g_Wkl);
    cudaGetSymbolAddress((void**)&hidh, g_hidh);
    cudaGetSymbolAddress((void**)&hidl, g_hidl);
    cudaGetSymbolAddress((void**)&x,    g_x);
    cudaGetSymbolAddress((void**)&hnh,  g_hnh);
    cudaGetSymbolAddress((void**)&hnl,  g_hnl);
    cudaGetSymbolAddress((void**)&kraw, g_kraw);
    cudaGetSymbolAddress((void**)&kns,  g_kns);
    cudaGetSymbolAddress((void**)&kne,  g_kne);
    cudaGetSymbolAddress((void**)&gram, g_gram);
    cudaGetSymbolAddress((void**)&c,    g_c);
    cudaGetSymbolAddress((void**)&r,    g_r);

    cudaFuncSetAttribute(gemm3_kernel<0>, cudaFuncAttributeMaxDynamicSharedMemorySize, GSMEM);
    cudaFuncSetAttribute(gemm3_kernel<1>, cudaFuncAttributeMaxDynamicSharedMemorySize, GSMEM);
    cudaFuncSetAttribute(gemm3_kernel<2>, cudaFuncAttributeMaxDynamicSharedMemorySize, GSMEM);

    split_all_kernel<<<1280, 256>>>(W1, W2, W_sem, W_epi, W1h, W1l, W2h, W2l, Wkh, Wkl);
    gather_kernel<<<TOK, H_>>>(seq, embed, h, hh, hl);
    // hid = relu(h @ W1^T + b1) -> bf16 split   [8192, 512]
    gemm3_kernel<1><<<dim3(H2_/GBN, TOK/GBM), 256, GSMEM>>>(
        hh, hl, W1h, W1l, b1, nullptr, nullptr, hidh, hidl, TOK, H2_, H_);
    // x = hid @ W2^T + b2 + h -> fp32           [8192, 256]
    gemm3_kernel<2><<<dim3(H_/GBN, TOK/GBM), 256, GSMEM>>>(
        hidh, hidl, W2h, W2l, b2, h, x, nullptr, nullptr, TOK, H_, H2_);
    ln_kernel<<<TOK/8, 256>>>(x, hnh, hnl, gamma, beta);
    // kraw = hn @ [W_sem; W_epi]^T -> fp32      [8192, 256]
    gemm3_kernel<0><<<dim3(H_/GBN, TOK/GBM), 256, GSMEM>>>(
        hnh, hnl, Wkh, Wkl, nullptr, nullptr, kraw, nullptr, nullptr, TOK, H_, H_);
    knorm_kernel<<<(B_*(L_-1)*2 + 7)/8, 256>>>(kraw, kns, kne);
    gram_kernel<<<(B_*2*NBLK + 7)/8, 256>>>(kns, kne, gram);
    scan_kernel<<<256, 256>>>(kraw, kns, kne, gram, c);
    rproj_kernel<<<B_, H_>>>(c, W_rp, b_rp, r);
    out_kernel<<<V_/128, 256>>>(r, W_out, b_out, out);
}